// round 9
// baseline (speedup 1.0000x reference)
#include <cuda_runtime.h>
#include <cuda_bf16.h>
#include <math.h>
#include <stdint.h>

#define N_NODES 100000
#define N_EDGES 1600000
#define IN_F    16
#define HID     100
#define OUTF    3

// A' smem: hi section [0,208) + lo section [208,416), row stride 424 bf16
#define SEC    208
#define NKF    39          // B gmem image: 3 sections x 13 kf
#define MT     80
#define THR    320         // 10 warps: 5 along M x 2 along N
#define NW     10
#define A_STR  424
#define SA_BYTES (MT * A_STR * 2)   // 67840

#define SCAN_B 1024
#define NBLK   ((N_NODES + SCAN_B - 1) / SCAN_B)   // 98

// ---------------------------------------------------------------------------
// Scratch (device globals; allocation APIs are forbidden)
// ---------------------------------------------------------------------------
__device__ __align__(16) float g_h  [N_NODES * HID];
__device__ __align__(16) float g_h2 [N_NODES * HID];
__device__ __align__(16) uint4 g_Bfrag[3 * NKF * 2 * 4 * 32];
// CSR scratch
__device__ int   g_cnt   [N_NODES];
__device__ int   g_rowptr[N_NODES + 1];
__device__ int   g_cur   [N_NODES];
__device__ int   g_bsum  [NBLK];
__device__ int   g_bsumex[NBLK];
__device__ __align__(16) uint2 g_edge[N_EDGES];   // {src, w bits} sorted by dst

__device__ __forceinline__ uint32_t smem_u32(const void* p) {
    uint32_t a;
    asm("{ .reg .u64 t; cvta.to.shared.u64 t, %1; cvt.u32.u64 %0, t; }" : "=r"(a) : "l"(p));
    return a;
}
__device__ __forceinline__ uint32_t bf2_u32(__nv_bfloat162 v) {
    return *reinterpret_cast<uint32_t*>(&v);
}

#define LDSM4(r, addr)                                                           \
    asm volatile("ldmatrix.sync.aligned.m8n8.x4.shared.b16 {%0,%1,%2,%3}, [%4];" \
                 : "=r"((r)[0]), "=r"((r)[1]), "=r"((r)[2]), "=r"((r)[3])        \
                 : "r"(addr))

#define MMA16816(acc, a, bx, by)                                                 \
    asm volatile("mma.sync.aligned.m16n8k16.row.col.f32.bf16.bf16.f32 "          \
                 "{%0,%1,%2,%3}, {%4,%5,%6,%7}, {%8,%9}, {%0,%1,%2,%3};"         \
                 : "+f"((acc)[0]), "+f"((acc)[1]), "+f"((acc)[2]), "+f"((acc)[3])\
                 : "r"((a)[0]), "r"((a)[1]), "r"((a)[2]), "r"((a)[3]),           \
                   "r"(bx), "r"(by))

// ---------------------------------------------------------------------------
// CSR build
// ---------------------------------------------------------------------------
__global__ __launch_bounds__(256)
void hist_kernel(const int* __restrict__ dst) {
    int e = blockIdx.x * 256 + threadIdx.x;
    if (e < N_EDGES) atomicAdd(&g_cnt[dst[e]], 1);
}

__global__ __launch_bounds__(SCAN_B)
void block_sum_kernel() {
    __shared__ int s[SCAN_B];
    int i = blockIdx.x * SCAN_B + threadIdx.x;
    s[threadIdx.x] = (i < N_NODES) ? g_cnt[i] : 0;
    __syncthreads();
    for (int st = SCAN_B / 2; st > 0; st >>= 1) {
        if (threadIdx.x < st) s[threadIdx.x] += s[threadIdx.x + st];
        __syncthreads();
    }
    if (threadIdx.x == 0) g_bsum[blockIdx.x] = s[0];
}

__global__ __launch_bounds__(128)
void scan_bsum_kernel() {
    __shared__ int s[128];
    int t = threadIdx.x;
    int c = (t < NBLK) ? g_bsum[t] : 0;
    s[t] = c;
    __syncthreads();
    for (int st = 1; st < 128; st <<= 1) {
        int v = (t >= st) ? s[t - st] : 0;
        __syncthreads();
        s[t] += v;
        __syncthreads();
    }
    if (t < NBLK) g_bsumex[t] = s[t] - c;   // exclusive
}

__global__ __launch_bounds__(SCAN_B)
void rowptr_kernel() {
    __shared__ int s[SCAN_B];
    int i = blockIdx.x * SCAN_B + threadIdx.x;
    int c = (i < N_NODES) ? g_cnt[i] : 0;
    s[threadIdx.x] = c;
    __syncthreads();
    for (int st = 1; st < SCAN_B; st <<= 1) {
        int v = (threadIdx.x >= st) ? s[threadIdx.x - st] : 0;
        __syncthreads();
        s[threadIdx.x] += v;
        __syncthreads();
    }
    if (i < N_NODES) {
        int excl = g_bsumex[blockIdx.x] + s[threadIdx.x] - c;
        g_rowptr[i] = excl;
        g_cur[i]    = excl;
        if (i == N_NODES - 1) g_rowptr[N_NODES] = excl + c;
    }
}

__global__ __launch_bounds__(256)
void fill_kernel(const int* __restrict__ src, const int* __restrict__ dst,
                 const float* __restrict__ ef) {
    int e = blockIdx.x * 256 + threadIdx.x;
    if (e >= N_EDGES) return;
    int p = atomicAdd(&g_cur[dst[e]], 1);
    g_edge[p] = make_uint2((unsigned)src[e], __float_as_uint(ef[e]));
}

// ---------------------------------------------------------------------------
// Prep: pack B' (= W^T with hi/hi/lo sections) into MMA B-fragment layout.
// ---------------------------------------------------------------------------
__device__ __forceinline__ __nv_bfloat16 wconv(const float* W, int sec, int kk, int col) {
    float w = (kk < 2 * HID && col < HID) ? W[kk * HID + col] : 0.0f;
    __nv_bfloat16 hi = __float2bfloat16(w);
    return (sec == 2) ? __float2bfloat16(w - __bfloat162float(hi)) : hi;
}

__global__ __launch_bounds__(256)
void prep_B_kernel(const float* __restrict__ W1, const float* __restrict__ W2,
                   const float* __restrict__ W3)
{
    int i = blockIdx.x * 256 + threadIdx.x;
    if (i >= 3 * NKF * 2 * 4 * 32) return;
    int l    = i / (NKF * 256);
    int r    = i - l * (NKF * 256);
    int kf   = r >> 8;
    int r2   = r & 255;
    int wn   = r2 >> 7;
    int nbp  = (r2 >> 5) & 3;
    int lane = r2 & 31;

    int sec = kf / 13;
    int kk0 = (kf - sec * 13) * 16 + (lane & 3) * 2;
    int n0  = wn * 64 + (nbp * 2) * 8 + (lane >> 2);
    int n1  = n0 + 8;

    const float* W = (l == 0) ? W1 : (l == 1) ? W2 : W3;

    uint4 o;
    o.x = bf2_u32(__nv_bfloat162(wconv(W, sec, kk0,     n0), wconv(W, sec, kk0 + 1, n0)));
    o.y = bf2_u32(__nv_bfloat162(wconv(W, sec, kk0 + 8, n0), wconv(W, sec, kk0 + 9, n0)));
    o.z = bf2_u32(__nv_bfloat162(wconv(W, sec, kk0,     n1), wconv(W, sec, kk0 + 1, n1)));
    o.w = bf2_u32(__nv_bfloat162(wconv(W, sec, kk0 + 8, n1), wconv(W, sec, kk0 + 9, n1)));
    g_Bfrag[i] = o;
}

// ---------------------------------------------------------------------------
// FUSED layer kernel: gather (CSR segment-sum) + GEMM + bias + relu.
//   out[n,0:100] = relu( concat(h[n], sum_e w_e h[src_e]) @ W + b )
// A' fill: cols 0..99 direct from h; cols 100..199 gathered via CSR,
// both converted to bf16 hi/lo in smem. Gather overlaps the co-resident
// CTA's MMA phase (2 CTAs/SM). MMA mainloop as round 8.
// ---------------------------------------------------------------------------
__global__ __launch_bounds__(THR, 2)
void mpl_fused(const float* __restrict__ h,
               const uint4* __restrict__ Bf,
               const float* __restrict__ b,
               float* __restrict__ out,
               int n_nodes)
{
    extern __shared__ __align__(16) uint8_t smem[];
    __nv_bfloat16* sA = reinterpret_cast<__nv_bfloat16*>(smem);
    const uint32_t sbase = smem_u32(smem);

    const int tid    = threadIdx.x;
    const int wid    = tid >> 5;
    const int lane   = tid & 31;
    const int warp_m = wid >> 1;         // 0..4
    const int warp_n = wid & 1;          // 0..1
    const int node0  = blockIdx.x * MT;

    // ---- fill part 1: h section (kk 0..99) + zero pad (kk 200..207) ----
    for (int i = tid; i < MT * 27; i += THR) {
        int row = i / 27;
        int j   = i - row * 27;
        int kk  = (j < 25) ? j * 4 : 200 + (j - 25) * 4;
        int n   = node0 + row;
        float4 v = make_float4(0.f, 0.f, 0.f, 0.f);
        if (j < 25 && n < n_nodes)
            v = *reinterpret_cast<const float4*>(h + (size_t)n * HID + kk);
        __nv_bfloat162 h0 = __floats2bfloat162_rn(v.x, v.y);
        __nv_bfloat162 h1 = __floats2bfloat162_rn(v.z, v.w);
        __nv_bfloat162 l0 = __floats2bfloat162_rn(v.x - __bfloat162float(h0.x),
                                                  v.y - __bfloat162float(h0.y));
        __nv_bfloat162 l1 = __floats2bfloat162_rn(v.z - __bfloat162float(h1.x),
                                                  v.w - __bfloat162float(h1.y));
        __nv_bfloat16* rp = sA + row * A_STR;
        *reinterpret_cast<uint2*>(rp + kk)       = make_uint2(bf2_u32(h0), bf2_u32(h1));
        *reinterpret_cast<uint2*>(rp + SEC + kk) = make_uint2(bf2_u32(l0), bf2_u32(l1));
    }

    // ---- fill part 2: gathered section (kk 100..199), warp-per-node ----
    for (int nl = wid; nl < MT; nl += NW) {
        const int n = node0 + nl;
        float4 acc = make_float4(0.f, 0.f, 0.f, 0.f);
        if (n < n_nodes) {
            int e  = g_rowptr[n];
            int e1 = g_rowptr[n + 1];
            for (; e + 4 <= e1; e += 4) {
                uint2 p0 = g_edge[e];
                uint2 p1 = g_edge[e + 1];
                uint2 p2 = g_edge[e + 2];
                uint2 p3 = g_edge[e + 3];
                if (lane < 25) {
                    float4 v0 = *reinterpret_cast<const float4*>(h + (size_t)p0.x * HID + lane * 4);
                    float4 v1 = *reinterpret_cast<const float4*>(h + (size_t)p1.x * HID + lane * 4);
                    float4 v2 = *reinterpret_cast<const float4*>(h + (size_t)p2.x * HID + lane * 4);
                    float4 v3 = *reinterpret_cast<const float4*>(h + (size_t)p3.x * HID + lane * 4);
                    float w0 = __uint_as_float(p0.y), w1 = __uint_as_float(p1.y);
                    float w2 = __uint_as_float(p2.y), w3 = __uint_as_float(p3.y);
                    acc.x += w0 * v0.x + w1 * v1.x + w2 * v2.x + w3 * v3.x;
                    acc.y += w0 * v0.y + w1 * v1.y + w2 * v2.y + w3 * v3.y;
                    acc.z += w0 * v0.z + w1 * v1.z + w2 * v2.z + w3 * v3.z;
                    acc.w += w0 * v0.w + w1 * v1.w + w2 * v2.w + w3 * v3.w;
                }
            }
            for (; e < e1; ++e) {
                uint2 p0 = g_edge[e];
                if (lane < 25) {
                    float4 v0 = *reinterpret_cast<const float4*>(h + (size_t)p0.x * HID + lane * 4);
                    float w0 = __uint_as_float(p0.y);
                    acc.x += w0 * v0.x; acc.y += w0 * v0.y;
                    acc.z += w0 * v0.z; acc.w += w0 * v0.w;
                }
            }
        }
        if (lane < 25) {
            __nv_bfloat162 h0 = __floats2bfloat162_rn(acc.x, acc.y);
            __nv_bfloat162 h1 = __floats2bfloat162_rn(acc.z, acc.w);
            __nv_bfloat162 l0 = __floats2bfloat162_rn(acc.x - __bfloat162float(h0.x),
                                                      acc.y - __bfloat162float(h0.y));
            __nv_bfloat162 l1 = __floats2bfloat162_rn(acc.z - __bfloat162float(h1.x),
                                                      acc.w - __bfloat162float(h1.y));
            __nv_bfloat16* rp = sA + nl * A_STR + 100 + lane * 4;
            *reinterpret_cast<uint2*>(rp)       = make_uint2(bf2_u32(h0), bf2_u32(h1));
            *reinterpret_cast<uint2*>(rp + SEC) = make_uint2(bf2_u32(l0), bf2_u32(l1));
        }
    }
    __syncthreads();

    // ---- MMA mainloop (round-8 structure) ----
    float acc[8][4];
#pragma unroll
    for (int f = 0; f < 8; ++f)
#pragma unroll
        for (int j = 0; j < 4; ++j) acc[f][j] = 0.0f;

    const int lrow  = lane & 15;
    const int lkoff = (lane >> 4) << 3;
    const uint32_t aHi = sbase + (uint32_t)(((warp_m * 16 + lrow) * A_STR + lkoff) * 2);
    const uint32_t aLo = aHi + SEC * 2;
    const uint4* bHi = Bf + (size_t)warp_n * 128 + lane;
    const uint4* bLo = Bf + (size_t)26 * 256 + (size_t)warp_n * 128 + lane;

    uint32_t ah[2][4], al[2][4];
    uint4 bb[2][4];

    // Phase 1: B_hi x (A_hi + A_lo)
    LDSM4(ah[0], aHi);
    LDSM4(al[0], aLo);
#pragma unroll
    for (int nbp = 0; nbp < 4; ++nbp) {
        bb[0][nbp] = bHi[nbp * 32];
        bb[1][nbp] = bHi[256 + nbp * 32];
    }
#pragma unroll
    for (int k = 0; k < 13; ++k) {
        const int cur = k & 1, nxt = cur ^ 1;
        if (k + 1 < 13) {
            LDSM4(ah[nxt], aHi + (uint32_t)((k + 1) * 32));
            LDSM4(al[nxt], aLo + (uint32_t)((k + 1) * 32));
        }
#pragma unroll
        for (int nbp = 0; nbp < 4; ++nbp) {
            const uint4 bv = bb[cur][nbp];
            MMA16816(acc[nbp * 2],     ah[cur], bv.x, bv.y);
            MMA16816(acc[nbp * 2 + 1], ah[cur], bv.z, bv.w);
            MMA16816(acc[nbp * 2],     al[cur], bv.x, bv.y);
            MMA16816(acc[nbp * 2 + 1], al[cur], bv.z, bv.w);
            if (k + 2 < 13) bb[cur][nbp] = bHi[(k + 2) * 256 + nbp * 32];
        }
    }

    // Phase 2: B_lo x A_hi
    LDSM4(ah[0], aHi);
#pragma unroll
    for (int nbp = 0; nbp < 4; ++nbp) {
        bb[0][nbp] = bLo[nbp * 32];
        bb[1][nbp] = bLo[256 + nbp * 32];
    }
#pragma unroll
    for (int k = 0; k < 13; ++k) {
        const int cur = k & 1, nxt = cur ^ 1;
        if (k + 1 < 13) LDSM4(ah[nxt], aHi + (uint32_t)((k + 1) * 32));
#pragma unroll
        for (int nbp = 0; nbp < 4; ++nbp) {
            const uint4 bv = bb[cur][nbp];
            MMA16816(acc[nbp * 2],     ah[cur], bv.x, bv.y);
            MMA16816(acc[nbp * 2 + 1], ah[cur], bv.z, bv.w);
            if (k + 2 < 13) bb[cur][nbp] = bLo[(k + 2) * 256 + nbp * 32];
        }
    }

    // ---- epilogue: bias + relu + float2 stores ----
    const int gr = lane >> 2;
    const int tc = lane & 3;
    const int r0 = node0 + warp_m * 16 + gr;
    const int r1 = r0 + 8;
#pragma unroll
    for (int f = 0; f < 8; ++f) {
        int col = warp_n * 64 + f * 8 + tc * 2;
        if (col < HID) {
            float b0 = b[col], b1 = b[col + 1];
            if (r0 < n_nodes) {
                float2 v;
                v.x = fmaxf(acc[f][0] + b0, 0.f);
                v.y = fmaxf(acc[f][1] + b1, 0.f);
                *reinterpret_cast<float2*>(out + (size_t)r0 * HID + col) = v;
            }
            if (r1 < n_nodes) {
                float2 v;
                v.x = fmaxf(acc[f][2] + b0, 0.f);
                v.y = fmaxf(acc[f][3] + b1, 0.f);
                *reinterpret_cast<float2*>(out + (size_t)r1 * HID + col) = v;
            }
        }
    }
}

// ---------------------------------------------------------------------------
// Lift GEMM (FFMA; tiny K=16): h = tanh(x @ W_lift + b_lift)
// ---------------------------------------------------------------------------
template <int KDIM>
__global__ __launch_bounds__(512, 1)
void lift_gemm_kernel(const float* __restrict__ in1,
                      const float* __restrict__ W,
                      const float* __restrict__ b,
                      float* __restrict__ out,
                      int n_nodes)
{
    extern __shared__ float sm[];
    constexpr int SSTR = KDIM + 4;
    float* sW  = sm;
    float* sIn = sm + KDIM * 128;

    const int tid   = threadIdx.x;
    const int node0 = blockIdx.x * 128;

    for (int i = tid; i < KDIM * 128; i += 512) {
        int k = i >> 7, c = i & 127;
        sW[i] = (c < HID) ? W[k * HID + c] : 0.0f;
    }
    for (int i = tid; i < 128 * KDIM; i += 512) {
        int nl = i / KDIM, k = i - nl * KDIM;
        int n  = node0 + nl;
        sIn[nl * SSTR + k] = (n < n_nodes) ? in1[n * KDIM + k] : 0.0f;
    }
    __syncthreads();

    const int lane = tid & 31;
    const int wp   = tid >> 5;
    const float* abase = sIn + wp * 8 * SSTR;
    const float* wbase = sW + lane * 4;

    float4 acc[8];
#pragma unroll
    for (int j = 0; j < 8; ++j) acc[j] = make_float4(0.f, 0.f, 0.f, 0.f);

#pragma unroll
    for (int k0 = 0; k0 < KDIM; k0 += 4) {
        const float4 w0 = *reinterpret_cast<const float4*>(wbase + (k0 + 0) * 128);
        const float4 w1 = *reinterpret_cast<const float4*>(wbase + (k0 + 1) * 128);
        const float4 w2 = *reinterpret_cast<const float4*>(wbase + (k0 + 2) * 128);
        const float4 w3 = *reinterpret_cast<const float4*>(wbase + (k0 + 3) * 128);
#pragma unroll
        for (int j = 0; j < 8; ++j) {
            const float4 a = *reinterpret_cast<const float4*>(abase + j * SSTR + k0);
            acc[j].x += a.x * w0.x; acc[j].y += a.x * w0.y; acc[j].z += a.x * w0.z; acc[j].w += a.x * w0.w;
            acc[j].x += a.y * w1.x; acc[j].y += a.y * w1.y; acc[j].z += a.y * w1.z; acc[j].w += a.y * w1.w;
            acc[j].x += a.z * w2.x; acc[j].y += a.z * w2.y; acc[j].z += a.z * w2.z; acc[j].w += a.z * w2.w;
            acc[j].x += a.w * w3.x; acc[j].y += a.w * w3.y; acc[j].z += a.w * w3.z; acc[j].w += a.w * w3.w;
        }
    }

    if (lane < 25) {
        const float4 bias = *reinterpret_cast<const float4*>(b + lane * 4);
#pragma unroll
        for (int j = 0; j < 8; ++j) {
            int n = node0 + wp * 8 + j;
            if (n < n_nodes) {
                float4 r;
                r.x = tanhf(acc[j].x + bias.x); r.y = tanhf(acc[j].y + bias.y);
                r.z = tanhf(acc[j].z + bias.z); r.w = tanhf(acc[j].w + bias.w);
                *reinterpret_cast<float4*>(out + (size_t)n * HID + lane * 4) = r;
            }
        }
    }
}

// ---------------------------------------------------------------------------
// Output head: y[n] = sigmoid(h[n,0:100] @ W_out[100x3] + b_out)
// ---------------------------------------------------------------------------
__global__ __launch_bounds__(256)
void out_kernel(const float* __restrict__ h,
                const float* __restrict__ Wo,
                const float* __restrict__ bo,
                float* __restrict__ y,
                int n_nodes)
{
    __shared__ float sW[HID * OUTF];
    int tid = threadIdx.x;
    for (int i = tid; i < HID * OUTF; i += 256) sW[i] = Wo[i];
    __syncthreads();

    int node = blockIdx.x * 256 + tid;
    if (node >= n_nodes) return;

    float a0 = bo[0], a1 = bo[1], a2 = bo[2];
    const float4* hv = reinterpret_cast<const float4*>(h + (size_t)node * HID);
#pragma unroll
    for (int kb = 0; kb < 25; ++kb) {
        float4 v = hv[kb];
        int k = kb * 4;
        a0 += v.x * sW[(k+0)*3+0]; a1 += v.x * sW[(k+0)*3+1]; a2 += v.x * sW[(k+0)*3+2];
        a0 += v.y * sW[(k+1)*3+0]; a1 += v.y * sW[(k+1)*3+1]; a2 += v.y * sW[(k+1)*3+2];
        a0 += v.z * sW[(k+2)*3+0]; a1 += v.z * sW[(k+2)*3+1]; a2 += v.z * sW[(k+2)*3+2];
        a0 += v.w * sW[(k+3)*3+0]; a1 += v.w * sW[(k+3)*3+1]; a2 += v.w * sW[(k+3)*3+2];
    }
    y[(size_t)node * 3 + 0] = 1.0f / (1.0f + expf(-a0));
    y[(size_t)node * 3 + 1] = 1.0f / (1.0f + expf(-a1));
    y[(size_t)node * 3 + 2] = 1.0f / (1.0f + expf(-a2));
}

// ---------------------------------------------------------------------------
extern "C" void kernel_launch(void* const* d_in, const int* in_sizes, int n_in,
                              void* d_out, int out_size)
{
    const float* x      = (const float*)d_in[0];
    const float* ef     = (const float*)d_in[1];
    const int*   src    = (const int*)  d_in[2];
    const int*   dst    = (const int*)  d_in[3];
    const float* W_lift = (const float*)d_in[4];
    const float* b_lift = (const float*)d_in[5];
    const float* W1     = (const float*)d_in[6];
    const float* b1     = (const float*)d_in[7];
    const float* W2     = (const float*)d_in[8];
    const float* b2     = (const float*)d_in[9];
    const float* W3     = (const float*)d_in[10];
    const float* b3     = (const float*)d_in[11];
    const float* W_out  = (const float*)d_in[12];
    const float* b_out  = (const float*)d_in[13];
    float* y = (float*)d_out;

    float *h, *h2;
    uint4* Bf;
    int* cnt;
    cudaGetSymbolAddress((void**)&h,   g_h);
    cudaGetSymbolAddress((void**)&h2,  g_h2);
    cudaGetSymbolAddress((void**)&Bf,  g_Bfrag);
    cudaGetSymbolAddress((void**)&cnt, g_cnt);

    const size_t SMEM_LIFT = (IN_F * 128 + 128 * (IN_F + 4)) * sizeof(float);

    cudaFuncSetAttribute((const void*)mpl_fused,
                         cudaFuncAttributeMaxDynamicSharedMemorySize, SA_BYTES);

    // 0) weight prep + CSR build (once per launch)
    prep_B_kernel<<<(3 * NKF * 256 + 255) / 256, 256>>>(W1, W2, W3);
    cudaMemsetAsync(cnt, 0, N_NODES * sizeof(int));
    hist_kernel<<<(N_EDGES + 255) / 256, 256>>>(dst);
    block_sum_kernel<<<NBLK, SCAN_B>>>();
    scan_bsum_kernel<<<1, 128>>>();
    rowptr_kernel<<<NBLK, SCAN_B>>>();
    fill_kernel<<<(N_EDGES + 255) / 256, 256>>>(src, dst, ef);

    // 1) lift
    lift_gemm_kernel<IN_F><<<(N_NODES + 127) / 128, 512, SMEM_LIFT>>>(
        x, W_lift, b_lift, h, N_NODES);

    const int MPL_GRID = (N_NODES + MT - 1) / MT;   // 1250

    const float* bs[3] = { b1, b2, b3 };
    float* bufs[4] = { h, h2, h, h2 };

    // 2) fused layers: gather + GEMM + relu in one kernel
    for (int l = 0; l < 3; ++l) {
        mpl_fused<<<MPL_GRID, THR, SA_BYTES>>>(
            bufs[l], Bf + (size_t)l * NKF * 256, bs[l], bufs[l + 1], N_NODES);
    }

    // 3) output head
    out_kernel<<<(N_NODES + 255) / 256, 256>>>(h2, W_out, b_out, y, N_NODES);

    (void)in_sizes; (void)n_in; (void)out_size;
}

// round 10
// speedup vs baseline: 1.0831x; 1.0831x over previous
#include <cuda_runtime.h>
#include <cuda_bf16.h>
#include <math.h>
#include <stdint.h>

#define N_NODES 100000
#define N_EDGES 1600000
#define IN_F    16
#define HID     100
#define OUTF    3

// A' smem: hi section [0,208) + lo section [208,416), row stride 424 bf16
#define SEC    208
#define NKF    39          // B gmem image: 3 sections x 13 kf
#define MT     64
#define THR    256         // 8 warps: 4 along M x 2 along N
#define A_STR  424
#define SA_BYTES (MT * A_STR * 2)   // 54272

#define SCAN_B 1024
#define NBLK   ((N_NODES + SCAN_B - 1) / SCAN_B)   // 98

// ---------------------------------------------------------------------------
// Scratch (device globals; allocation APIs are forbidden)
// ---------------------------------------------------------------------------
__device__ __align__(16) float g_h  [N_NODES * HID];
__device__ __align__(16) float g_h2 [N_NODES * HID];
__device__ __align__(16) float g_red[N_NODES * HID];
__device__ __align__(16) uint4 g_Bfrag[3 * NKF * 2 * 4 * 32];
// CSR scratch
__device__ int   g_cnt   [N_NODES];
__device__ int   g_rowptr[N_NODES + 1];
__device__ int   g_cur   [N_NODES];
__device__ int   g_bsum  [NBLK];
__device__ int   g_bsumex[NBLK];
__device__ __align__(16) uint2 g_edge[N_EDGES];   // {src, w bits} sorted by dst

__device__ __forceinline__ uint32_t smem_u32(const void* p) {
    uint32_t a;
    asm("{ .reg .u64 t; cvta.to.shared.u64 t, %1; cvt.u32.u64 %0, t; }" : "=r"(a) : "l"(p));
    return a;
}
__device__ __forceinline__ uint32_t bf2_u32(__nv_bfloat162 v) {
    return *reinterpret_cast<uint32_t*>(&v);
}

#define LDSM4(r, addr)                                                           \
    asm volatile("ldmatrix.sync.aligned.m8n8.x4.shared.b16 {%0,%1,%2,%3}, [%4];" \
                 : "=r"((r)[0]), "=r"((r)[1]), "=r"((r)[2]), "=r"((r)[3])        \
                 : "r"(addr))

#define MMA16816(acc, a, bx, by)                                                 \
    asm volatile("mma.sync.aligned.m16n8k16.row.col.f32.bf16.bf16.f32 "          \
                 "{%0,%1,%2,%3}, {%4,%5,%6,%7}, {%8,%9}, {%0,%1,%2,%3};"         \
                 : "+f"((acc)[0]), "+f"((acc)[1]), "+f"((acc)[2]), "+f"((acc)[3])\
                 : "r"((a)[0]), "r"((a)[1]), "r"((a)[2]), "r"((a)[3]),           \
                   "r"(bx), "r"(by))

// ---------------------------------------------------------------------------
// CSR build
// ---------------------------------------------------------------------------
__global__ __launch_bounds__(256)
void hist_kernel(const int* __restrict__ dst) {
    int e = blockIdx.x * 256 + threadIdx.x;
    if (e < N_EDGES) atomicAdd(&g_cnt[dst[e]], 1);
}

__global__ __launch_bounds__(SCAN_B)
void block_sum_kernel() {
    __shared__ int s[SCAN_B];
    int i = blockIdx.x * SCAN_B + threadIdx.x;
    s[threadIdx.x] = (i < N_NODES) ? g_cnt[i] : 0;
    __syncthreads();
    for (int st = SCAN_B / 2; st > 0; st >>= 1) {
        if (threadIdx.x < st) s[threadIdx.x] += s[threadIdx.x + st];
        __syncthreads();
    }
    if (threadIdx.x == 0) g_bsum[blockIdx.x] = s[0];
}

__global__ __launch_bounds__(128)
void scan_bsum_kernel() {
    __shared__ int s[128];
    int t = threadIdx.x;
    int c = (t < NBLK) ? g_bsum[t] : 0;
    s[t] = c;
    __syncthreads();
    for (int st = 1; st < 128; st <<= 1) {
        int v = (t >= st) ? s[t - st] : 0;
        __syncthreads();
        s[t] += v;
        __syncthreads();
    }
    if (t < NBLK) g_bsumex[t] = s[t] - c;   // exclusive
}

__global__ __launch_bounds__(SCAN_B)
void rowptr_kernel() {
    __shared__ int s[SCAN_B];
    int i = blockIdx.x * SCAN_B + threadIdx.x;
    int c = (i < N_NODES) ? g_cnt[i] : 0;
    s[threadIdx.x] = c;
    __syncthreads();
    for (int st = 1; st < SCAN_B; st <<= 1) {
        int v = (threadIdx.x >= st) ? s[threadIdx.x - st] : 0;
        __syncthreads();
        s[threadIdx.x] += v;
        __syncthreads();
    }
    if (i < N_NODES) {
        int excl = g_bsumex[blockIdx.x] + s[threadIdx.x] - c;
        g_rowptr[i] = excl;
        g_cur[i]    = excl;
        if (i == N_NODES - 1) g_rowptr[N_NODES] = excl + c;
    }
}

__global__ __launch_bounds__(256)
void fill_kernel(const int* __restrict__ src, const int* __restrict__ dst,
                 const float* __restrict__ ef) {
    int e = blockIdx.x * 256 + threadIdx.x;
    if (e >= N_EDGES) return;
    int p = atomicAdd(&g_cur[dst[e]], 1);
    g_edge[p] = make_uint2((unsigned)src[e], __float_as_uint(ef[e]));
}

// ---------------------------------------------------------------------------
// Gather-reduce (CSR segment sum): red[n] = sum_e w_e * h[src_e]
// One warp per node; lanes 0..24 own one float4 column chunk each.
// ---------------------------------------------------------------------------
__global__ __launch_bounds__(256)
void gather_kernel(const float* __restrict__ h, float* __restrict__ red) {
    const int wid  = threadIdx.x >> 5;
    const int lane = threadIdx.x & 31;
    const int n    = blockIdx.x * 8 + wid;
    if (n >= N_NODES) return;

    const int e0 = g_rowptr[n];
    const int e1 = g_rowptr[n + 1];
    float4 acc = make_float4(0.f, 0.f, 0.f, 0.f);

    int e = e0;
    for (; e + 2 <= e1; e += 2) {
        uint2 p0 = g_edge[e];
        uint2 p1 = g_edge[e + 1];
        float w0 = __uint_as_float(p0.y);
        float w1 = __uint_as_float(p1.y);
        if (lane < 25) {
            float4 v0 = *reinterpret_cast<const float4*>(h + (size_t)p0.x * HID + lane * 4);
            float4 v1 = *reinterpret_cast<const float4*>(h + (size_t)p1.x * HID + lane * 4);
            acc.x += w0 * v0.x + w1 * v1.x;
            acc.y += w0 * v0.y + w1 * v1.y;
            acc.z += w0 * v0.z + w1 * v1.z;
            acc.w += w0 * v0.w + w1 * v1.w;
        }
    }
    if (e < e1) {
        uint2 p0 = g_edge[e];
        float w0 = __uint_as_float(p0.y);
        if (lane < 25) {
            float4 v0 = *reinterpret_cast<const float4*>(h + (size_t)p0.x * HID + lane * 4);
            acc.x += w0 * v0.x; acc.y += w0 * v0.y;
            acc.z += w0 * v0.z; acc.w += w0 * v0.w;
        }
    }
    if (lane < 25)
        *reinterpret_cast<float4*>(red + (size_t)n * HID + lane * 4) = acc;
}

// ---------------------------------------------------------------------------
// Prep: pack B' (= W^T with hi/hi/lo sections) into MMA B-fragment layout.
// ---------------------------------------------------------------------------
__device__ __forceinline__ __nv_bfloat16 wconv(const float* W, int sec, int kk, int col) {
    float w = (kk < 2 * HID && col < HID) ? W[kk * HID + col] : 0.0f;
    __nv_bfloat16 hi = __float2bfloat16(w);
    return (sec == 2) ? __float2bfloat16(w - __bfloat162float(hi)) : hi;
}

__global__ __launch_bounds__(256)
void prep_B_kernel(const float* __restrict__ W1, const float* __restrict__ W2,
                   const float* __restrict__ W3)
{
    int i = blockIdx.x * 256 + threadIdx.x;
    if (i >= 3 * NKF * 2 * 4 * 32) return;
    int l    = i / (NKF * 256);
    int r    = i - l * (NKF * 256);
    int kf   = r >> 8;
    int r2   = r & 255;
    int wn   = r2 >> 7;
    int nbp  = (r2 >> 5) & 3;
    int lane = r2 & 31;

    int sec = kf / 13;
    int kk0 = (kf - sec * 13) * 16 + (lane & 3) * 2;
    int n0  = wn * 64 + (nbp * 2) * 8 + (lane >> 2);
    int n1  = n0 + 8;

    const float* W = (l == 0) ? W1 : (l == 1) ? W2 : W3;

    uint4 o;
    o.x = bf2_u32(__nv_bfloat162(wconv(W, sec, kk0,     n0), wconv(W, sec, kk0 + 1, n0)));
    o.y = bf2_u32(__nv_bfloat162(wconv(W, sec, kk0 + 8, n0), wconv(W, sec, kk0 + 9, n0)));
    o.z = bf2_u32(__nv_bfloat162(wconv(W, sec, kk0,     n1), wconv(W, sec, kk0 + 1, n1)));
    o.w = bf2_u32(__nv_bfloat162(wconv(W, sec, kk0 + 8, n1), wconv(W, sec, kk0 + 9, n1)));
    g_Bfrag[i] = o;
}

// ---------------------------------------------------------------------------
// MPL GEMM: out[n,0:100] = relu( concat(h[n], red[n]) @ W + b )
// Round-8 mainloop (phased B reuse, distance-2 register prefetch), resized
// to MT=64 / 8 warps so 3 CTAs fit per SM (24 warps -> better latency hiding).
// ---------------------------------------------------------------------------
__global__ __launch_bounds__(THR, 3)
void mpl_gemm_mma(const float* __restrict__ h,
                  const float* __restrict__ red,
                  const uint4* __restrict__ Bf,
                  const float* __restrict__ b,
                  float* __restrict__ out,
                  int n_nodes)
{
    extern __shared__ __align__(16) uint8_t smem[];
    __nv_bfloat16* sA = reinterpret_cast<__nv_bfloat16*>(smem);
    const uint32_t sbase = smem_u32(smem);

    const int tid    = threadIdx.x;
    const int wid    = tid >> 5;
    const int lane   = tid & 31;
    const int warp_m = wid >> 1;         // 0..3
    const int warp_n = wid & 1;          // 0..1
    const int node0  = blockIdx.x * MT;

    // ---- fill A' once: hi at [0,208), lo at [208,416) ----
    for (int i = tid; i < MT * 52; i += THR) {
        int row = i / 52;
        int kk  = (i - row * 52) * 4;
        int n   = node0 + row;
        float4 v = make_float4(0.f, 0.f, 0.f, 0.f);
        if (n < n_nodes) {
            if (kk < HID)          v = *reinterpret_cast<const float4*>(h + (size_t)n * HID + kk);
            else if (kk < 2 * HID) v = *reinterpret_cast<const float4*>(red + (size_t)n * HID + kk - HID);
        }
        __nv_bfloat162 h0 = __floats2bfloat162_rn(v.x, v.y);
        __nv_bfloat162 h1 = __floats2bfloat162_rn(v.z, v.w);
        __nv_bfloat162 l0 = __floats2bfloat162_rn(v.x - __bfloat162float(h0.x),
                                                  v.y - __bfloat162float(h0.y));
        __nv_bfloat162 l1 = __floats2bfloat162_rn(v.z - __bfloat162float(h1.x),
                                                  v.w - __bfloat162float(h1.y));
        __nv_bfloat16* rp = sA + row * A_STR;
        *reinterpret_cast<uint2*>(rp + kk)       = make_uint2(bf2_u32(h0), bf2_u32(h1));
        *reinterpret_cast<uint2*>(rp + SEC + kk) = make_uint2(bf2_u32(l0), bf2_u32(l1));
    }
    __syncthreads();

    float acc[8][4];
#pragma unroll
    for (int f = 0; f < 8; ++f)
#pragma unroll
        for (int j = 0; j < 4; ++j) acc[f][j] = 0.0f;

    const int lrow  = lane & 15;
    const int lkoff = (lane >> 4) << 3;
    const uint32_t aHi = sbase + (uint32_t)(((warp_m * 16 + lrow) * A_STR + lkoff) * 2);
    const uint32_t aLo = aHi + SEC * 2;
    const uint4* bHi = Bf + (size_t)warp_n * 128 + lane;                // kf 0..12
    const uint4* bLo = Bf + (size_t)26 * 256 + (size_t)warp_n * 128 + lane;

    uint32_t ah[2][4], al[2][4];
    uint4 bb[2][4];

    // ================= Phase 1: B_hi x (A_hi + A_lo) =================
    LDSM4(ah[0], aHi);
    LDSM4(al[0], aLo);
#pragma unroll
    for (int nbp = 0; nbp < 4; ++nbp) {
        bb[0][nbp] = bHi[nbp * 32];
        bb[1][nbp] = bHi[256 + nbp * 32];
    }
#pragma unroll
    for (int k = 0; k < 13; ++k) {
        const int cur = k & 1, nxt = cur ^ 1;
        if (k + 1 < 13) {
            LDSM4(ah[nxt], aHi + (uint32_t)((k + 1) * 32));
            LDSM4(al[nxt], aLo + (uint32_t)((k + 1) * 32));
        }
#pragma unroll
        for (int nbp = 0; nbp < 4; ++nbp) {
            const uint4 bv = bb[cur][nbp];
            MMA16816(acc[nbp * 2],     ah[cur], bv.x, bv.y);
            MMA16816(acc[nbp * 2 + 1], ah[cur], bv.z, bv.w);
            MMA16816(acc[nbp * 2],     al[cur], bv.x, bv.y);
            MMA16816(acc[nbp * 2 + 1], al[cur], bv.z, bv.w);
            if (k + 2 < 13) bb[cur][nbp] = bHi[(k + 2) * 256 + nbp * 32];
        }
    }

    // ================= Phase 2: B_lo x A_hi =================
    LDSM4(ah[0], aHi);
#pragma unroll
    for (int nbp = 0; nbp < 4; ++nbp) {
        bb[0][nbp] = bLo[nbp * 32];
        bb[1][nbp] = bLo[256 + nbp * 32];
    }
#pragma unroll
    for (int k = 0; k < 13; ++k) {
        const int cur = k & 1, nxt = cur ^ 1;
        if (k + 1 < 13) LDSM4(ah[nxt], aHi + (uint32_t)((k + 1) * 32));
#pragma unroll
        for (int nbp = 0; nbp < 4; ++nbp) {
            const uint4 bv = bb[cur][nbp];
            MMA16816(acc[nbp * 2],     ah[cur], bv.x, bv.y);
            MMA16816(acc[nbp * 2 + 1], ah[cur], bv.z, bv.w);
            if (k + 2 < 13) bb[cur][nbp] = bLo[(k + 2) * 256 + nbp * 32];
        }
    }

    // ---- epilogue: bias + relu + float2 stores ----
    const int gr = lane >> 2;
    const int tc = lane & 3;
    const int r0 = node0 + warp_m * 16 + gr;
    const int r1 = r0 + 8;
#pragma unroll
    for (int f = 0; f < 8; ++f) {
        int col = warp_n * 64 + f * 8 + tc * 2;
        if (col < HID) {
            float b0 = b[col], b1 = b[col + 1];
            if (r0 < n_nodes) {
                float2 v;
                v.x = fmaxf(acc[f][0] + b0, 0.f);
                v.y = fmaxf(acc[f][1] + b1, 0.f);
                *reinterpret_cast<float2*>(out + (size_t)r0 * HID + col) = v;
            }
            if (r1 < n_nodes) {
                float2 v;
                v.x = fmaxf(acc[f][2] + b0, 0.f);
                v.y = fmaxf(acc[f][3] + b1, 0.f);
                *reinterpret_cast<float2*>(out + (size_t)r1 * HID + col) = v;
            }
        }
    }
}

// ---------------------------------------------------------------------------
// Lift GEMM (FFMA; tiny K=16): h = tanh(x @ W_lift + b_lift)
// ---------------------------------------------------------------------------
template <int KDIM>
__global__ __launch_bounds__(512, 1)
void lift_gemm_kernel(const float* __restrict__ in1,
                      const float* __restrict__ W,
                      const float* __restrict__ b,
                      float* __restrict__ out,
                      int n_nodes)
{
    extern __shared__ float sm[];
    constexpr int SSTR = KDIM + 4;
    float* sW  = sm;
    float* sIn = sm + KDIM * 128;

    const int tid   = threadIdx.x;
    const int node0 = blockIdx.x * 128;

    for (int i = tid; i < KDIM * 128; i += 512) {
        int k = i >> 7, c = i & 127;
        sW[i] = (c < HID) ? W[k * HID + c] : 0.0f;
    }
    for (int i = tid; i < 128 * KDIM; i += 512) {
        int nl = i / KDIM, k = i - nl * KDIM;
        int n  = node0 + nl;
        sIn[nl * SSTR + k] = (n < n_nodes) ? in1[n * KDIM + k] : 0.0f;
    }
    __syncthreads();

    const int lane = tid & 31;
    const int wp   = tid >> 5;
    const float* abase = sIn + wp * 8 * SSTR;
    const float* wbase = sW + lane * 4;

    float4 acc[8];
#pragma unroll
    for (int j = 0; j < 8; ++j) acc[j] = make_float4(0.f, 0.f, 0.f, 0.f);

#pragma unroll
    for (int k0 = 0; k0 < KDIM; k0 += 4) {
        const float4 w0 = *reinterpret_cast<const float4*>(wbase + (k0 + 0) * 128);
        const float4 w1 = *reinterpret_cast<const float4*>(wbase + (k0 + 1) * 128);
        const float4 w2 = *reinterpret_cast<const float4*>(wbase + (k0 + 2) * 128);
        const float4 w3 = *reinterpret_cast<const float4*>(wbase + (k0 + 3) * 128);
#pragma unroll
        for (int j = 0; j < 8; ++j) {
            const float4 a = *reinterpret_cast<const float4*>(abase + j * SSTR + k0);
            acc[j].x += a.x * w0.x; acc[j].y += a.x * w0.y; acc[j].z += a.x * w0.z; acc[j].w += a.x * w0.w;
            acc[j].x += a.y * w1.x; acc[j].y += a.y * w1.y; acc[j].z += a.y * w1.z; acc[j].w += a.y * w1.w;
            acc[j].x += a.z * w2.x; acc[j].y += a.z * w2.y; acc[j].z += a.z * w2.z; acc[j].w += a.z * w2.w;
            acc[j].x += a.w * w3.x; acc[j].y += a.w * w3.y; acc[j].z += a.w * w3.z; acc[j].w += a.w * w3.w;
        }
    }

    if (lane < 25) {
        const float4 bias = *reinterpret_cast<const float4*>(b + lane * 4);
#pragma unroll
        for (int j = 0; j < 8; ++j) {
            int n = node0 + wp * 8 + j;
            if (n < n_nodes) {
                float4 r;
                r.x = tanhf(acc[j].x + bias.x); r.y = tanhf(acc[j].y + bias.y);
                r.z = tanhf(acc[j].z + bias.z); r.w = tanhf(acc[j].w + bias.w);
                *reinterpret_cast<float4*>(out + (size_t)n * HID + lane * 4) = r;
            }
        }
    }
}

// ---------------------------------------------------------------------------
// Output head: y[n] = sigmoid(h[n,0:100] @ W_out[100x3] + b_out)
// ---------------------------------------------------------------------------
__global__ __launch_bounds__(256)
void out_kernel(const float* __restrict__ h,
                const float* __restrict__ Wo,
                const float* __restrict__ bo,
                float* __restrict__ y,
                int n_nodes)
{
    __shared__ float sW[HID * OUTF];
    int tid = threadIdx.x;
    for (int i = tid; i < HID * OUTF; i += 256) sW[i] = Wo[i];
    __syncthreads();

    int node = blockIdx.x * 256 + tid;
    if (node >= n_nodes) return;

    float a0 = bo[0], a1 = bo[1], a2 = bo[2];
    const float4* hv = reinterpret_cast<const float4*>(h + (size_t)node * HID);
#pragma unroll
    for (int kb = 0; kb < 25; ++kb) {
        float4 v = hv[kb];
        int k = kb * 4;
        a0 += v.x * sW[(k+0)*3+0]; a1 += v.x * sW[(k+0)*3+1]; a2 += v.x * sW[(k+0)*3+2];
        a0 += v.y * sW[(k+1)*3+0]; a1 += v.y * sW[(k+1)*3+1]; a2 += v.y * sW[(k+1)*3+2];
        a0 += v.z * sW[(k+2)*3+0]; a1 += v.z * sW[(k+2)*3+1]; a2 += v.z * sW[(k+2)*3+2];
        a0 += v.w * sW[(k+3)*3+0]; a1 += v.w * sW[(k+3)*3+1]; a2 += v.w * sW[(k+3)*3+2];
    }
    y[(size_t)node * 3 + 0] = 1.0f / (1.0f + expf(-a0));
    y[(size_t)node * 3 + 1] = 1.0f / (1.0f + expf(-a1));
    y[(size_t)node * 3 + 2] = 1.0f / (1.0f + expf(-a2));
}

// ---------------------------------------------------------------------------
extern "C" void kernel_launch(void* const* d_in, const int* in_sizes, int n_in,
                              void* d_out, int out_size)
{
    const float* x      = (const float*)d_in[0];
    const float* ef     = (const float*)d_in[1];
    const int*   src    = (const int*)  d_in[2];
    const int*   dst    = (const int*)  d_in[3];
    const float* W_lift = (const float*)d_in[4];
    const float* b_lift = (const float*)d_in[5];
    const float* W1     = (const float*)d_in[6];
    const float* b1     = (const float*)d_in[7];
    const float* W2     = (const float*)d_in[8];
    const float* b2     = (const float*)d_in[9];
    const float* W3     = (const float*)d_in[10];
    const float* b3     = (const float*)d_in[11];
    const float* W_out  = (const float*)d_in[12];
    const float* b_out  = (const float*)d_in[13];
    float* y = (float*)d_out;

    float *h, *h2, *red;
    uint4* Bf;
    int* cnt;
    cudaGetSymbolAddress((void**)&h,   g_h);
    cudaGetSymbolAddress((void**)&h2,  g_h2);
    cudaGetSymbolAddress((void**)&red, g_red);
    cudaGetSymbolAddress((void**)&Bf,  g_Bfrag);
    cudaGetSymbolAddress((void**)&cnt, g_cnt);

    const size_t SMEM_LIFT = (IN_F * 128 + 128 * (IN_F + 4)) * sizeof(float);

    cudaFuncSetAttribute((const void*)mpl_gemm_mma,
                         cudaFuncAttributeMaxDynamicSharedMemorySize, SA_BYTES);

    // 0) weight prep + CSR build (once per launch)
    prep_B_kernel<<<(3 * NKF * 256 + 255) / 256, 256>>>(W1, W2, W3);
    cudaMemsetAsync(cnt, 0, N_NODES * sizeof(int));
    hist_kernel<<<(N_EDGES + 255) / 256, 256>>>(dst);
    block_sum_kernel<<<NBLK, SCAN_B>>>();
    scan_bsum_kernel<<<1, 128>>>();
    rowptr_kernel<<<NBLK, SCAN_B>>>();
    fill_kernel<<<(N_EDGES + 255) / 256, 256>>>(src, dst, ef);

    // 1) lift
    lift_gemm_kernel<IN_F><<<(N_NODES + 127) / 128, 512, SMEM_LIFT>>>(
        x, W_lift, b_lift, h, N_NODES);

    const int MPL_GRID    = (N_NODES + MT - 1) / MT;   // 1563
    const int GATHER_GRID = (N_NODES + 7) / 8;          // 12500

    const float* bs[3] = { b1, b2, b3 };
    float* bufs[4] = { h, h2, h, h2 };

    for (int l = 0; l < 3; ++l) {
        float* hin  = bufs[l];
        float* hout = bufs[l + 1];
        gather_kernel<<<GATHER_GRID, 256>>>(hin, red);
        mpl_gemm_mma<<<MPL_GRID, THR, SA_BYTES>>>(
            hin, red, Bf + (size_t)l * NKF * 256, bs[l], hout, N_NODES);
    }

    // 3) output head
    out_kernel<<<(N_NODES + 255) / 256, 256>>>(h2, W_out, b_out, y, N_NODES);

    (void)in_sizes; (void)n_in; (void)out_size;
}